// round 3
// baseline (speedup 1.0000x reference)
#include <cuda_runtime.h>
#include <cstdint>

// Shapes (fixed by the problem instance)
#define B_  4
#define H_  96
#define W_  96
#define D_  96
#define C_  32
#define NWH 12            // 96/8
#define NUM_WIN 1728      // 12*12*12
#define LEN_KEEP 691      // int(1728*0.4)
#define ELEMS_PER_OUT (B_*H_*W_*D_*C_)   // 113,246,208 floats
#define NSEG (B_*H_*W_*NWH)              // 442,368 segments of 64 float4

// per-segment mask: segment s covers float4 indices [s*64, s*64+64)
// (= 8 voxels along d of one window, all 32 channels). 1 = masked, 0 = kept.
__device__ float g_segmask[NSEG];

// ---------------------------------------------------------------------------
// Kernel 1: per-window keep/mask via stable rank (argsort-equivalent), then
// expand each window's mask to its 64 (h,w)-segments directly.
// grid = (B_, 27), block = 256: 4 threads per window (j split 4x432 + shfl).
// ---------------------------------------------------------------------------
__global__ void __launch_bounds__(256)
winmask_kernel(const float* __restrict__ noise) {
    __shared__ float sn[NUM_WIN];
    const int b = blockIdx.x;
    const float* nb = noise + b * NUM_WIN;
    for (int t = threadIdx.x; t < NUM_WIN; t += 256)
        sn[t] = nb[t];
    __syncthreads();

    const int i      = blockIdx.y * 64 + (threadIdx.x >> 2);  // window index
    const int jchunk = threadIdx.x & 3;
    const float v = sn[i];

    int rank = 0;
    const int j0 = jchunk * 432;
#pragma unroll 4
    for (int j = j0; j < j0 + 432; j++) {
        const float u = sn[j];
        // stable-argsort tie-break: earlier index wins on equality
        rank += (u < v) || (u == v && j < i);
    }
    rank += __shfl_xor_sync(0xFFFFFFFFu, rank, 1);
    rank += __shfl_xor_sync(0xFFFFFFFFu, rank, 2);
    const float m = (rank < LEN_KEEP) ? 0.0f : 1.0f;
    // all 4 lanes of this window's group get m (rank only complete after xor
    // pair — every lane has the full sum already, so m is valid on all 4)

    // Expand: window i = (wh3, ww3, wd3); its segments are
    // g = ((b*96 + wh3*8 + dh)*96 + ww3*8 + dw)*12 + wd3, dh,dw in [0,8)
    const int wd3 = i % NWH;
    const int r   = i / NWH;
    const int ww3 = r % NWH;
    const int wh3 = r / NWH;
    const int gbase = ((b * H_ + wh3 * 8) * W_ + ww3 * 8) * NWH + wd3;
#pragma unroll
    for (int s = jchunk * 16; s < jchunk * 16 + 16; s++) {
        const int dh = s >> 3;
        const int dw = s & 7;
        g_segmask[gbase + dh * (W_ * NWH) + dw * NWH] = m;
    }
}

// ---------------------------------------------------------------------------
// Kernel 2: pure stream. 2 float4 per thread; mask lookup is a single shift +
// L1-resident broadcast load; x load predicated off warp-uniformly for masked
// segments (60% of read traffic skipped). No div/mod, no branches around
// stores.
// ---------------------------------------------------------------------------
__global__ void __launch_bounds__(256)
mask_expand_kernel(const float4* __restrict__ x,
                   float4* __restrict__ out_xm,
                   float4* __restrict__ out_mk) {
    const int i0 = blockIdx.x * 512 + threadIdx.x;
    const int i1 = i0 + 256;

    const float m0 = __ldg(&g_segmask[i0 >> 6]);
    const float m1 = __ldg(&g_segmask[i1 >> 6]);

    float4 a = make_float4(0.f, 0.f, 0.f, 0.f);
    float4 b = make_float4(0.f, 0.f, 0.f, 0.f);
    if (m0 == 0.0f) a = x[i0];   // warp-uniform predicate
    if (m1 == 0.0f) b = x[i1];

    out_xm[i0] = a;
    out_mk[i0] = make_float4(m0, m0, m0, m0);
    out_xm[i1] = b;
    out_mk[i1] = make_float4(m1, m1, m1, m1);
}

extern "C" void kernel_launch(void* const* d_in, const int* in_sizes, int n_in,
                              void* d_out, int out_size) {
    const float* x     = (const float*)d_in[0];   // [B,H,W,D,C] fp32
    const float* noise = (const float*)d_in[1];   // [B, 1728]   fp32
    float* out = (float*)d_out;                   // [x_masked | mask]

    {
        dim3 grid(B_, 27);
        winmask_kernel<<<grid, 256>>>(noise);
    }
    {
        const int n4     = ELEMS_PER_OUT / 4;     // 28,311,552
        const int blocks = n4 / 512;              // 55,296 exactly
        mask_expand_kernel<<<blocks, 256>>>(
            (const float4*)x,
            (float4*)out,
            (float4*)(out + (long long)ELEMS_PER_OUT));
    }
}

// round 4
// speedup vs baseline: 1.0217x; 1.0217x over previous
#include <cuda_runtime.h>
#include <cstdint>

// Shapes (fixed by the problem instance)
#define B_  4
#define H_  96
#define W_  96
#define D_  96
#define C_  32
#define NWH 12            // 96/8
#define NUM_WIN 1728      // 12*12*12
#define LEN_KEEP 691      // int(1728*0.4)
#define ELEMS_PER_OUT (B_*H_*W_*D_*C_)   // 113,246,208 floats
#define NSEG (B_*H_*W_*NWH)              // 442,368 segments of 64 float4

// per-segment mask: segment s covers float4 indices [s*64, s*64+64)
// (= 8 voxels along d of one window, all 32 channels). 1 = masked, 0 = kept.
__device__ float g_segmask[NSEG];

// ---------------------------------------------------------------------------
// Kernel 1: per-window keep/mask via stable rank (argsort-equivalent), then
// expand each window's mask to its 64 (h,w)-segments.
// grid = (B_, 54), block = 256: 8 threads per window (j split 8x216 + shfl).
// ---------------------------------------------------------------------------
__global__ void __launch_bounds__(256)
winmask_kernel(const float* __restrict__ noise) {
    __shared__ float sn[NUM_WIN];
    const int b = blockIdx.x;
    const float* nb = noise + b * NUM_WIN;
    for (int t = threadIdx.x; t < NUM_WIN; t += 256)
        sn[t] = nb[t];
    __syncthreads();

    const int i      = blockIdx.y * 32 + (threadIdx.x >> 3);  // window index
    const int jchunk = threadIdx.x & 7;
    const float v = sn[i];

    int rank = 0;
    const int j0 = jchunk * 216;
#pragma unroll 4
    for (int j = j0; j < j0 + 216; j++) {
        const float u = sn[j];
        // stable-argsort tie-break: earlier index wins on equality
        rank += (u < v) || (u == v && j < i);
    }
    rank += __shfl_xor_sync(0xFFFFFFFFu, rank, 1);
    rank += __shfl_xor_sync(0xFFFFFFFFu, rank, 2);
    rank += __shfl_xor_sync(0xFFFFFFFFu, rank, 4);
    const float m = (rank < LEN_KEEP) ? 0.0f : 1.0f;

    // Expand: window i = (wh3, ww3, wd3); its 64 segments are
    // g = ((b*96 + wh3*8 + dh)*96 + ww3*8 + dw)*12 + wd3, dh,dw in [0,8)
    const int wd3 = i % NWH;
    const int r   = i / NWH;
    const int ww3 = r % NWH;
    const int wh3 = r / NWH;
    const int gbase = ((b * H_ + wh3 * 8) * W_ + ww3 * 8) * NWH + wd3;
#pragma unroll
    for (int s = jchunk * 8; s < jchunk * 8 + 8; s++) {
        const int dh = s >> 3;
        const int dw = s & 7;
        g_segmask[gbase + dh * (W_ * NWH) + dw * NWH] = m;
    }
}

// ---------------------------------------------------------------------------
// Kernel 2: pure stream. 4 float4 per thread; all (predicated) x loads issued
// before any store (MLP=4). Mask lookup is one shift + L1-resident broadcast
// load; x read skipped warp-uniformly for masked segments (60% of reads).
// Streaming cache hints on the one-shot data.
// ---------------------------------------------------------------------------
__global__ void __launch_bounds__(256)
mask_expand_kernel(const float4* __restrict__ x,
                   float4* __restrict__ out_xm,
                   float4* __restrict__ out_mk) {
    const int base = blockIdx.x * 1024 + threadIdx.x;

    float  m[4];
    float4 v[4];
#pragma unroll
    for (int k = 0; k < 4; k++)
        m[k] = __ldg(&g_segmask[(base + k * 256) >> 6]);

#pragma unroll
    for (int k = 0; k < 4; k++) {
        v[k] = make_float4(0.f, 0.f, 0.f, 0.f);
        if (m[k] == 0.0f)
            v[k] = __ldcs(&x[base + k * 256]);   // warp-uniform predicate
    }

#pragma unroll
    for (int k = 0; k < 4; k++) {
        const int i = base + k * 256;
        __stcs(&out_xm[i], v[k]);
        __stcs(&out_mk[i], make_float4(m[k], m[k], m[k], m[k]));
    }
}

extern "C" void kernel_launch(void* const* d_in, const int* in_sizes, int n_in,
                              void* d_out, int out_size) {
    const float* x     = (const float*)d_in[0];   // [B,H,W,D,C] fp32
    const float* noise = (const float*)d_in[1];   // [B, 1728]   fp32
    float* out = (float*)d_out;                   // [x_masked | mask]

    {
        dim3 grid(B_, 54);
        winmask_kernel<<<grid, 256>>>(noise);
    }
    {
        const int n4     = ELEMS_PER_OUT / 4;     // 28,311,552
        const int blocks = n4 / 1024;             // 27,648 exactly
        mask_expand_kernel<<<blocks, 256>>>(
            (const float4*)x,
            (float4*)out,
            (float4*)(out + (long long)ELEMS_PER_OUT));
    }
}

// round 5
// speedup vs baseline: 1.0587x; 1.0362x over previous
#include <cuda_runtime.h>
#include <cstdint>

// Shapes (fixed by the problem instance)
#define B_  4
#define H_  96
#define W_  96
#define D_  96
#define C_  32
#define NWH 12            // 96/8
#define NUM_WIN 1728      // 12*12*12
#define LEN_KEEP 691      // int(1728*0.4)
#define LEN_MASK (NUM_WIN - LEN_KEEP)    // 1037
#define ELEMS_PER_OUT (B_*H_*W_*D_*C_)   // 113,246,208 floats

#define MASKED_BLOCKS (B_ * LEN_MASK * 4)   // 16,592
#define KEPT_BLOCKS   (B_ * LEN_KEEP * 4)   // 11,056

// window mask: 1 = masked, 0 = kept
__device__ float g_winmask[B_ * NUM_WIN];
// window-ordered compact lists of global window ids (b*1728+i)
__device__ int g_kept_list[B_ * LEN_KEEP];
__device__ int g_masked_list[B_ * LEN_MASK];

// ---------------------------------------------------------------------------
// Kernel 1: per-window keep/mask via stable rank (argsort-equivalent).
// grid = (B_, 54), block = 256: 8 threads per window (j split 8x216 + shfl).
// ---------------------------------------------------------------------------
__global__ void __launch_bounds__(256)
winmask_kernel(const float* __restrict__ noise) {
    __shared__ float sn[NUM_WIN];
    const int b = blockIdx.x;
    const float* nb = noise + b * NUM_WIN;
    for (int t = threadIdx.x; t < NUM_WIN; t += 256)
        sn[t] = nb[t];
    __syncthreads();

    const int i      = blockIdx.y * 32 + (threadIdx.x >> 3);  // window index
    const int jchunk = threadIdx.x & 7;
    const float v = sn[i];

    int rank = 0;
    const int j0 = jchunk * 216;
#pragma unroll 4
    for (int j = j0; j < j0 + 216; j++) {
        const float u = sn[j];
        // stable-argsort tie-break: earlier index wins on equality
        rank += (u < v) || (u == v && j < i);
    }
    rank += __shfl_xor_sync(0xFFFFFFFFu, rank, 1);
    rank += __shfl_xor_sync(0xFFFFFFFFu, rank, 2);
    rank += __shfl_xor_sync(0xFFFFFFFFu, rank, 4);

    if (jchunk == 0)
        g_winmask[b * NUM_WIN + i] = (rank < LEN_KEEP) ? 0.0f : 1.0f;
}

// ---------------------------------------------------------------------------
// Kernel 2: window-ordered compaction into kept/masked lists via block scan.
// grid = B_, block = 216 threads (each owns 8 consecutive windows).
// ---------------------------------------------------------------------------
__global__ void __launch_bounds__(216)
scan_kernel() {
    __shared__ int psum[216];
    const int b = blockIdx.x;
    const int t = threadIdx.x;
    const int base = t * 8;

    float mv[8];
    int cnt = 0;
#pragma unroll
    for (int k = 0; k < 8; k++) {
        mv[k] = g_winmask[b * NUM_WIN + base + k];
        cnt += (mv[k] == 0.0f);
    }
    psum[t] = cnt;
    __syncthreads();

    // Hillis-Steele inclusive scan over 216 thread sums
    for (int off = 1; off < 216; off <<= 1) {
        int v = (t >= off) ? psum[t - off] : 0;
        __syncthreads();
        psum[t] += v;
        __syncthreads();
    }

    int kp = psum[t] - cnt;   // kept windows strictly before this chunk
#pragma unroll
    for (int k = 0; k < 8; k++) {
        const int j = base + k;
        if (mv[k] == 0.0f) {
            g_kept_list[b * LEN_KEEP + kp] = b * NUM_WIN + j;
            kp++;
        } else {
            g_masked_list[b * LEN_MASK + (j - kp)] = b * NUM_WIN + j;
        }
    }
}

// ---------------------------------------------------------------------------
// Kernel 3: phase kernel. Blocks [0, MASKED_BLOCKS) handle masked windows
// (pure write: xm=0, mk=1); remaining blocks handle kept windows (copy x,
// mk=0). Each block = one quarter-window: 16 segments of 64 float4 (1 KB)
// per output. bid ordering gives a natural write-only phase followed by a
// uniform 1R:2W phase.
// ---------------------------------------------------------------------------
__global__ void __launch_bounds__(256)
phase_kernel(const float4* __restrict__ x,
             float4* __restrict__ out_xm,
             float4* __restrict__ out_mk) {
    const int bid = blockIdx.x;
    const bool is_masked = (bid < MASKED_BLOCKS);

    int wglob, quarter;
    if (is_masked) {
        wglob   = __ldg(&g_masked_list[bid >> 2]);
        quarter = bid & 3;
    } else {
        const int k = bid - MASKED_BLOCKS;
        wglob   = __ldg(&g_kept_list[k >> 2]);
        quarter = k & 3;
    }

    const int b   = wglob / NUM_WIN;
    const int i   = wglob - b * NUM_WIN;
    const int wd3 = i % NWH;
    const int r   = i / NWH;
    const int ww3 = r % NWH;
    const int wh3 = r / NWH;

    const int t      = threadIdx.x;
    const int seg    = quarter * 16 + (t >> 4);   // 0..63 within window
    const int lane16 = t & 15;
    const int dh = seg >> 3;
    const int dw = seg & 7;
    const int h  = wh3 * 8 + dh;
    const int w  = ww3 * 8 + dw;
    // float4 base of this segment (8 voxels along d, 32 channels)
    const int s0 = (((b * H_ + h) * W_ + w) * D_ + wd3 * 8) * 8;

    if (is_masked) {
        const float4 z = make_float4(0.f, 0.f, 0.f, 0.f);
        const float4 o = make_float4(1.f, 1.f, 1.f, 1.f);
#pragma unroll
        for (int k = 0; k < 4; k++) {
            const int idx = s0 + lane16 + k * 16;
            __stcs(&out_xm[idx], z);
            __stcs(&out_mk[idx], o);
        }
    } else {
        float4 v[4];
#pragma unroll
        for (int k = 0; k < 4; k++)
            v[k] = __ldcs(&x[s0 + lane16 + k * 16]);
        const float4 z = make_float4(0.f, 0.f, 0.f, 0.f);
#pragma unroll
        for (int k = 0; k < 4; k++) {
            const int idx = s0 + lane16 + k * 16;
            __stcs(&out_xm[idx], v[k]);
            __stcs(&out_mk[idx], z);
        }
    }
}

extern "C" void kernel_launch(void* const* d_in, const int* in_sizes, int n_in,
                              void* d_out, int out_size) {
    const float* x     = (const float*)d_in[0];   // [B,H,W,D,C] fp32
    const float* noise = (const float*)d_in[1];   // [B, 1728]   fp32
    float* out = (float*)d_out;                   // [x_masked | mask]

    {
        dim3 grid(B_, 54);
        winmask_kernel<<<grid, 256>>>(noise);
    }
    scan_kernel<<<B_, 216>>>();
    phase_kernel<<<MASKED_BLOCKS + KEPT_BLOCKS, 256>>>(
        (const float4*)x,
        (float4*)out,
        (float4*)(out + (long long)ELEMS_PER_OUT));
}

// round 6
// speedup vs baseline: 1.0884x; 1.0281x over previous
#include <cuda_runtime.h>
#include <cstdint>

// Shapes (fixed by the problem instance)
#define B_  4
#define H_  96
#define W_  96
#define D_  96
#define C_  32
#define NWH 12            // 96/8
#define NUM_WIN 1728      // 12*12*12
#define LEN_KEEP 691      // int(1728*0.4)
#define KSEL (LEN_KEEP-1) // 0-indexed rank of the threshold key
#define LEN_MASK (NUM_WIN - LEN_KEEP)    // 1037
#define ELEMS_PER_OUT (B_*H_*W_*D_*C_)   // 113,246,208 floats

#define MASKED_BLOCKS (B_ * LEN_MASK * 4)   // 16,592
#define KEPT_BLOCKS   (B_ * LEN_KEEP * 4)   // 11,056

// window-ordered compact lists of global window ids (b*1728+i)
__device__ int g_kept_list[B_ * LEN_KEEP];
__device__ int g_masked_list[B_ * LEN_MASK];

// ---------------------------------------------------------------------------
// Kernel 1 (prep): O(n) selection + compaction, one block per batch.
//  1. key_i = (float_bits(noise_i) << 11) | i  — monotone, stable tie-break.
//  2. histogram on bucket = floor(noise*2048) (uniform occupancy), block scan
//     of 2048 counts -> bucket containing rank 690, tiny in-bucket select
//     -> threshold key (the 691st-smallest key).
//  3. kept_i = (key_i <= threshold); window-ordered compaction into lists.
// ---------------------------------------------------------------------------
__global__ void __launch_bounds__(1024)
prep_kernel(const float* __restrict__ noise) {
    __shared__ unsigned int sbits[NUM_WIN];
    __shared__ int hist[2048];
    __shared__ int wsum[32];
    __shared__ int s_bucket, s_below;
    __shared__ unsigned long long cand[128];
    __shared__ int cand_cnt;
    __shared__ unsigned long long s_thresh;

    const int b   = blockIdx.x;
    const int tid = threadIdx.x;
    const int lane = tid & 31;
    const int wid  = tid >> 5;

    for (int t = tid; t < NUM_WIN; t += 1024)
        sbits[t] = __float_as_uint(noise[b * NUM_WIN + t]);
    hist[tid] = 0; hist[tid + 1024] = 0;
    if (tid == 0) cand_cnt = 0;
    __syncthreads();

    for (int t = tid; t < NUM_WIN; t += 1024) {
        float v = __uint_as_float(sbits[t]);
        int bk = (int)(v * 2048.0f);
        bk = bk < 0 ? 0 : (bk > 2047 ? 2047 : bk);
        atomicAdd(&hist[bk], 1);
    }
    __syncthreads();

    // ---- scan of 2048 bucket counts (2 buckets per thread) ----
    const int a0 = hist[2 * tid], a1 = hist[2 * tid + 1];
    const int ts = a0 + a1;
    int v = ts;
#pragma unroll
    for (int o = 1; o < 32; o <<= 1) {
        int u = __shfl_up_sync(0xFFFFFFFFu, v, o);
        if (lane >= o) v += u;
    }
    if (lane == 31) wsum[wid] = v;
    __syncthreads();
    if (wid == 0) {
        int w = wsum[lane];
#pragma unroll
        for (int o = 1; o < 32; o <<= 1) {
            int u = __shfl_up_sync(0xFFFFFFFFu, w, o);
            if (lane >= o) w += u;
        }
        wsum[lane] = w;
    }
    __syncthreads();
    const int incl = v + (wid > 0 ? wsum[wid - 1] : 0);
    const int excl_pair = incl - ts;
    if (KSEL >= excl_pair && KSEL < excl_pair + a0) { s_bucket = 2 * tid;     s_below = excl_pair; }
    const int e1 = excl_pair + a0;
    if (KSEL >= e1 && KSEL < e1 + a1)               { s_bucket = 2 * tid + 1; s_below = e1; }
    __syncthreads();

    // ---- gather candidates in the target bucket, rank them exactly ----
    const int tb = s_bucket;
    for (int t = tid; t < NUM_WIN; t += 1024) {
        float fv = __uint_as_float(sbits[t]);
        int bk = (int)(fv * 2048.0f);
        bk = bk < 0 ? 0 : (bk > 2047 ? 2047 : bk);
        if (bk == tb) {
            int p = atomicAdd(&cand_cnt, 1);
            if (p < 128)
                cand[p] = ((unsigned long long)sbits[t] << 11) | (unsigned)t;
        }
    }
    __syncthreads();
    const int m = cand_cnt < 128 ? cand_cnt : 128;
    const int need = KSEL - s_below;
    if (tid < m) {
        unsigned long long k = cand[tid];
        int c = 0;
        for (int j = 0; j < m; j++) c += (cand[j] < k);
        if (c == need) s_thresh = k;
    }
    __syncthreads();
    const unsigned long long thresh = s_thresh;

    // ---- window-ordered compaction: 864 threads x 2 consecutive windows ----
    int cnt = 0, kept0 = 0, kept1 = 0;
    if (tid < 864) {
        const int j0 = 2 * tid, j1 = 2 * tid + 1;
        unsigned long long k0 = ((unsigned long long)sbits[j0] << 11) | (unsigned)j0;
        unsigned long long k1 = ((unsigned long long)sbits[j1] << 11) | (unsigned)j1;
        kept0 = (k0 <= thresh);
        kept1 = (k1 <= thresh);
        cnt = kept0 + kept1;
    }
    int v2 = cnt;
#pragma unroll
    for (int o = 1; o < 32; o <<= 1) {
        int u = __shfl_up_sync(0xFFFFFFFFu, v2, o);
        if (lane >= o) v2 += u;
    }
    if (lane == 31 && wid < 27) wsum[wid] = v2;
    __syncthreads();
    if (wid == 0) {
        int w = (lane < 27) ? wsum[lane] : 0;
#pragma unroll
        for (int o = 1; o < 32; o <<= 1) {
            int u = __shfl_up_sync(0xFFFFFFFFu, w, o);
            if (lane >= o) w += u;
        }
        if (lane < 27) wsum[lane] = w;
    }
    __syncthreads();
    if (tid < 864) {
        const int incl2 = v2 + (wid > 0 ? wsum[wid - 1] : 0);
        const int excl  = incl2 - cnt;          // kept windows before 2*tid
        const int j0 = 2 * tid, j1 = 2 * tid + 1;
        const int gw = b * NUM_WIN;
        if (kept0) g_kept_list[b * LEN_KEEP + excl]        = gw + j0;
        else       g_masked_list[b * LEN_MASK + (j0 - excl)] = gw + j0;
        const int kb1 = excl + kept0;
        if (kept1) g_kept_list[b * LEN_KEEP + kb1]         = gw + j1;
        else       g_masked_list[b * LEN_MASK + (j1 - kb1)]  = gw + j1;
    }
}

// ---------------------------------------------------------------------------
// Kernel 2: phase kernel. Blocks [0, MASKED_BLOCKS) handle masked windows
// (pure write: xm=0, mk=1); remaining blocks handle kept windows (copy x,
// mk=0). Each block = one quarter-window. PDL: launched with programmatic
// stream serialization; syncs on prep's completion right before list read.
// ---------------------------------------------------------------------------
__global__ void __launch_bounds__(256)
phase_kernel(const float4* __restrict__ x,
             float4* __restrict__ out_xm,
             float4* __restrict__ out_mk) {
    const int bid = blockIdx.x;
    const bool is_masked = (bid < MASKED_BLOCKS);
    const int k       = is_masked ? bid : (bid - MASKED_BLOCKS);
    const int lk      = k >> 2;
    const int quarter = k & 3;

    const int t      = threadIdx.x;
    const int seg    = quarter * 16 + (t >> 4);   // 0..63 within window
    const int lane16 = t & 15;
    const int dh = seg >> 3;
    const int dw = seg & 7;

    cudaGridDependencySynchronize();   // PDL: wait for prep's lists

    const int wglob = is_masked ? __ldg(&g_masked_list[lk])
                                : __ldg(&g_kept_list[lk]);

    const int b   = wglob / NUM_WIN;
    const int i   = wglob - b * NUM_WIN;
    const int wd3 = i % NWH;
    const int r   = i / NWH;
    const int ww3 = r % NWH;
    const int wh3 = r / NWH;

    const int h  = wh3 * 8 + dh;
    const int w  = ww3 * 8 + dw;
    // float4 base of this segment (8 voxels along d, 32 channels)
    const int s0 = (((b * H_ + h) * W_ + w) * D_ + wd3 * 8) * 8;

    if (is_masked) {
        const float4 z = make_float4(0.f, 0.f, 0.f, 0.f);
        const float4 o = make_float4(1.f, 1.f, 1.f, 1.f);
#pragma unroll
        for (int kk = 0; kk < 4; kk++) {
            const int idx = s0 + lane16 + kk * 16;
            __stcs(&out_xm[idx], z);
            __stcs(&out_mk[idx], o);
        }
    } else {
        float4 vv[4];
#pragma unroll
        for (int kk = 0; kk < 4; kk++)
            vv[kk] = __ldcs(&x[s0 + lane16 + kk * 16]);
        const float4 z = make_float4(0.f, 0.f, 0.f, 0.f);
#pragma unroll
        for (int kk = 0; kk < 4; kk++) {
            const int idx = s0 + lane16 + kk * 16;
            __stcs(&out_xm[idx], vv[kk]);
            __stcs(&out_mk[idx], z);
        }
    }
}

extern "C" void kernel_launch(void* const* d_in, const int* in_sizes, int n_in,
                              void* d_out, int out_size) {
    const float* x     = (const float*)d_in[0];   // [B,H,W,D,C] fp32
    const float* noise = (const float*)d_in[1];   // [B, 1728]   fp32
    float* out = (float*)d_out;                   // [x_masked | mask]

    prep_kernel<<<B_, 1024>>>(noise);

    // PDL launch: phase kernel may launch while prep runs; it blocks at
    // cudaGridDependencySynchronize() until prep's writes are visible.
    cudaLaunchConfig_t cfg = {};
    cfg.gridDim  = dim3(MASKED_BLOCKS + KEPT_BLOCKS);
    cfg.blockDim = dim3(256);
    cudaLaunchAttribute attrs[1];
    attrs[0].id = cudaLaunchAttributeProgrammaticStreamSerialization;
    attrs[0].val.programmaticStreamSerializationAllowed = 1;
    cfg.attrs = attrs;
    cfg.numAttrs = 1;
    cudaLaunchKernelEx(&cfg, phase_kernel,
                       (const float4*)x,
                       (float4*)out,
                       (float4*)(out + (long long)ELEMS_PER_OUT));
}

// round 7
// speedup vs baseline: 1.1173x; 1.0266x over previous
#include <cuda_runtime.h>
#include <cstdint>

// Shapes (fixed by the problem instance)
#define B_  4
#define H_  96
#define W_  96
#define D_  96
#define C_  32
#define NWH 12            // 96/8
#define NUM_WIN 1728      // 12*12*12
#define LEN_KEEP 691      // int(1728*0.4)
#define KSEL (LEN_KEEP-1) // 0-indexed rank of the threshold key
#define LEN_MASK (NUM_WIN - LEN_KEEP)    // 1037
#define ELEMS_PER_OUT (B_*H_*W_*D_*C_)   // 113,246,208 floats

// block phases: each block handles ONE output stream of ONE window (64 KB)
#define COPY_BLOCKS (B_ * LEN_KEEP)   // 2764: kept -> xm copy (1R:1W)
#define ONES_BLOCKS (B_ * LEN_MASK)   // 4148: masked -> mk = 1 (pure write)
#define ZM_BLOCKS   (B_ * LEN_MASK)   // 4148: masked -> xm = 0 (pure write)
#define ZK_BLOCKS   (B_ * LEN_KEEP)   // 2764: kept  -> mk = 0 (pure write)
#define TOTAL_BLOCKS (COPY_BLOCKS + ONES_BLOCKS + ZM_BLOCKS + ZK_BLOCKS) // 13824

// window-ordered compact lists of global window ids (b*1728+i)
__device__ int g_kept_list[B_ * LEN_KEEP];
__device__ int g_masked_list[B_ * LEN_MASK];

// ---------------------------------------------------------------------------
// Kernel 1 (prep): O(n) selection + compaction, one block per batch.
//  1. key_i = (float_bits(noise_i) << 11) | i  — monotone, stable tie-break.
//  2. histogram on bucket = floor(noise*2048), block scan of 2048 counts ->
//     bucket containing rank 690, exact in-bucket select -> threshold key.
//  3. kept_i = (key_i <= threshold); window-ordered compaction into lists.
// ---------------------------------------------------------------------------
__global__ void __launch_bounds__(1024)
prep_kernel(const float* __restrict__ noise) {
    __shared__ unsigned int sbits[NUM_WIN];
    __shared__ int hist[2048];
    __shared__ int wsum[32];
    __shared__ int s_bucket, s_below;
    __shared__ unsigned long long cand[128];
    __shared__ int cand_cnt;
    __shared__ unsigned long long s_thresh;

    const int b   = blockIdx.x;
    const int tid = threadIdx.x;
    const int lane = tid & 31;
    const int wid  = tid >> 5;

    for (int t = tid; t < NUM_WIN; t += 1024)
        sbits[t] = __float_as_uint(noise[b * NUM_WIN + t]);
    hist[tid] = 0; hist[tid + 1024] = 0;
    if (tid == 0) cand_cnt = 0;
    __syncthreads();

    for (int t = tid; t < NUM_WIN; t += 1024) {
        float v = __uint_as_float(sbits[t]);
        int bk = (int)(v * 2048.0f);
        bk = bk < 0 ? 0 : (bk > 2047 ? 2047 : bk);
        atomicAdd(&hist[bk], 1);
    }
    __syncthreads();

    // ---- scan of 2048 bucket counts (2 buckets per thread) ----
    const int a0 = hist[2 * tid], a1 = hist[2 * tid + 1];
    const int ts = a0 + a1;
    int v = ts;
#pragma unroll
    for (int o = 1; o < 32; o <<= 1) {
        int u = __shfl_up_sync(0xFFFFFFFFu, v, o);
        if (lane >= o) v += u;
    }
    if (lane == 31) wsum[wid] = v;
    __syncthreads();
    if (wid == 0) {
        int w = wsum[lane];
#pragma unroll
        for (int o = 1; o < 32; o <<= 1) {
            int u = __shfl_up_sync(0xFFFFFFFFu, w, o);
            if (lane >= o) w += u;
        }
        wsum[lane] = w;
    }
    __syncthreads();
    const int incl = v + (wid > 0 ? wsum[wid - 1] : 0);
    const int excl_pair = incl - ts;
    if (KSEL >= excl_pair && KSEL < excl_pair + a0) { s_bucket = 2 * tid;     s_below = excl_pair; }
    const int e1 = excl_pair + a0;
    if (KSEL >= e1 && KSEL < e1 + a1)               { s_bucket = 2 * tid + 1; s_below = e1; }
    __syncthreads();

    // ---- gather candidates in the target bucket, rank them exactly ----
    const int tb = s_bucket;
    for (int t = tid; t < NUM_WIN; t += 1024) {
        float fv = __uint_as_float(sbits[t]);
        int bk = (int)(fv * 2048.0f);
        bk = bk < 0 ? 0 : (bk > 2047 ? 2047 : bk);
        if (bk == tb) {
            int p = atomicAdd(&cand_cnt, 1);
            if (p < 128)
                cand[p] = ((unsigned long long)sbits[t] << 11) | (unsigned)t;
        }
    }
    __syncthreads();
    const int m = cand_cnt < 128 ? cand_cnt : 128;
    const int need = KSEL - s_below;
    if (tid < m) {
        unsigned long long k = cand[tid];
        int c = 0;
        for (int j = 0; j < m; j++) c += (cand[j] < k);
        if (c == need) s_thresh = k;
    }
    __syncthreads();
    const unsigned long long thresh = s_thresh;

    // ---- window-ordered compaction: 864 threads x 2 consecutive windows ----
    int cnt = 0, kept0 = 0, kept1 = 0;
    if (tid < 864) {
        const int j0 = 2 * tid, j1 = 2 * tid + 1;
        unsigned long long k0 = ((unsigned long long)sbits[j0] << 11) | (unsigned)j0;
        unsigned long long k1 = ((unsigned long long)sbits[j1] << 11) | (unsigned)j1;
        kept0 = (k0 <= thresh);
        kept1 = (k1 <= thresh);
        cnt = kept0 + kept1;
    }
    int v2 = cnt;
#pragma unroll
    for (int o = 1; o < 32; o <<= 1) {
        int u = __shfl_up_sync(0xFFFFFFFFu, v2, o);
        if (lane >= o) v2 += u;
    }
    if (lane == 31 && wid < 27) wsum[wid] = v2;
    __syncthreads();
    if (wid == 0) {
        int w = (lane < 27) ? wsum[lane] : 0;
#pragma unroll
        for (int o = 1; o < 32; o <<= 1) {
            int u = __shfl_up_sync(0xFFFFFFFFu, w, o);
            if (lane >= o) w += u;
        }
        if (lane < 27) wsum[lane] = w;
    }
    __syncthreads();
    if (tid < 864) {
        const int incl2 = v2 + (wid > 0 ? wsum[wid - 1] : 0);
        const int excl  = incl2 - cnt;          // kept windows before 2*tid
        const int j0 = 2 * tid, j1 = 2 * tid + 1;
        const int gw = b * NUM_WIN;
        if (kept0) g_kept_list[b * LEN_KEEP + excl]          = gw + j0;
        else       g_masked_list[b * LEN_MASK + (j0 - excl)]   = gw + j0;
        const int kb1 = excl + kept0;
        if (kept1) g_kept_list[b * LEN_KEEP + kb1]           = gw + j1;
        else       g_masked_list[b * LEN_MASK + (j1 - kb1)]    = gw + j1;
    }
}

// ---------------------------------------------------------------------------
// Kernel 2: phase kernel, single-stream blocks. Each block = ONE output
// stream of ONE full window (64 segments x 1 KB = 64 KB).
//   bid ranges: [copy kept->xm][ones masked->mk][zeros masked->xm]
//               [zeros kept->mk]
// 3 of 4 phases are data-free constant stores (725 MB pure write); only the
// copy phase reads x. 512 threads, 8 float4 per thread.
// ---------------------------------------------------------------------------
__global__ void __launch_bounds__(512)
phase_kernel(const float4* __restrict__ x,
             float4* __restrict__ out_xm,
             float4* __restrict__ out_mk) {
    const int bid = blockIdx.x;

    int phase, lk;
    if (bid < COPY_BLOCKS)                          { phase = 0; lk = bid; }
    else if (bid < COPY_BLOCKS + ONES_BLOCKS)       { phase = 1; lk = bid - COPY_BLOCKS; }
    else if (bid < COPY_BLOCKS + 2 * ONES_BLOCKS)   { phase = 2; lk = bid - COPY_BLOCKS - ONES_BLOCKS; }
    else                                            { phase = 3; lk = bid - COPY_BLOCKS - 2 * ONES_BLOCKS; }
    const bool from_masked = (phase == 1) || (phase == 2);

    const int t     = threadIdx.x;
    const int seg   = t >> 3;          // 0..63 window segment
    const int lane8 = t & 7;
    const int dh = seg >> 3;
    const int dw = seg & 7;

    cudaGridDependencySynchronize();   // PDL: wait for prep's lists

    const int wglob = from_masked ? __ldg(&g_masked_list[lk])
                                  : __ldg(&g_kept_list[lk]);

    const int b   = wglob / NUM_WIN;
    const int i   = wglob - b * NUM_WIN;
    const int wd3 = i % NWH;
    const int r   = i / NWH;
    const int ww3 = r % NWH;
    const int wh3 = r / NWH;

    const int h = wh3 * 8 + dh;
    const int w = ww3 * 8 + dw;
    // float4 base of this segment (8 voxels along d, 32 channels = 64 float4)
    const int s0 = (((b * H_ + h) * W_ + w) * D_ + wd3 * 8) * 8 + lane8;

    if (phase == 0) {
        // kept: copy x -> xm
        float4 v[8];
#pragma unroll
        for (int k = 0; k < 8; k++)
            v[k] = __ldcs(&x[s0 + k * 8]);
#pragma unroll
        for (int k = 0; k < 8; k++)
            __stcs(&out_xm[s0 + k * 8], v[k]);
    } else {
        const float fv = (phase == 1) ? 1.0f : 0.0f;
        const float4 c = make_float4(fv, fv, fv, fv);
        float4* outp = (phase == 2) ? out_xm : out_mk;
#pragma unroll
        for (int k = 0; k < 8; k++)
            __stcs(&outp[s0 + k * 8], c);
    }
}

extern "C" void kernel_launch(void* const* d_in, const int* in_sizes, int n_in,
                              void* d_out, int out_size) {
    const float* x     = (const float*)d_in[0];   // [B,H,W,D,C] fp32
    const float* noise = (const float*)d_in[1];   // [B, 1728]   fp32
    float* out = (float*)d_out;                   // [x_masked | mask]

    prep_kernel<<<B_, 1024>>>(noise);

    // PDL launch: phase kernel may launch while prep runs; blocks wait at
    // cudaGridDependencySynchronize() until prep's writes are visible.
    cudaLaunchConfig_t cfg = {};
    cfg.gridDim  = dim3(TOTAL_BLOCKS);
    cfg.blockDim = dim3(512);
    cudaLaunchAttribute attrs[1];
    attrs[0].id = cudaLaunchAttributeProgrammaticStreamSerialization;
    attrs[0].val.programmaticStreamSerializationAllowed = 1;
    cfg.attrs = attrs;
    cfg.numAttrs = 1;
    cudaLaunchKernelEx(&cfg, phase_kernel,
                       (const float4*)x,
                       (float4*)out,
                       (float4*)(out + (long long)ELEMS_PER_OUT));
}